// round 3
// baseline (speedup 1.0000x reference)
#include <cuda_runtime.h>
#include <cuda.h>
#include <cstdint>

// ============================================================================
// Problem constants
// ============================================================================
#define NN      8192
#define DD      128

// GEMM config (Ampere-style mma.sync tf32; baseline PTX, compiles for sm_100)
#define BM      64
#define BN      128
#define BK      32
#define STAGES  4
#define NKT     (NN / BK)      // 256 K iterations
#define GTHREADS 256

// SMEM tile strides (floats); +4 pad keeps LDS conflict-free and 16B-aligned rows
#define APAD    36             // 32 + 4
#define AS_FLOATS (BM * APAD)          // 2304
#define BS_FLOATS (BN * APAD)          // 4608
#define STAGE_FLOATS (AS_FLOATS + BS_FLOATS)   // 6912
#define SMEM_TOTAL (STAGES * STAGE_FLOATS * 4) // 110592 bytes

// ============================================================================
// Scratch (device globals; allocation-free)
// ============================================================================
__device__ __align__(1024) float g_h[NN * DD];
__device__ __align__(1024) float g_g[NN * DD];
__device__ __align__(1024) float g_gT[DD * NN];
__device__ __align__(128)  float g_d[NN];
__device__ __align__(128)  float g_e[NN];

// ============================================================================
// PTX helpers
// ============================================================================
__device__ __forceinline__ uint32_t smem_u32(const void* p) {
    uint32_t a;
    asm("{ .reg .u64 t; cvta.to.shared.u64 t, %1; cvt.u32.u64 %0, t; }" : "=r"(a) : "l"(p));
    return a;
}

__device__ __forceinline__ void cp16(uint32_t dst, const void* src) {
    asm volatile("cp.async.cg.shared.global [%0], [%1], 16;" :: "r"(dst), "l"(src));
}

#define CP_COMMIT()  asm volatile("cp.async.commit_group;" ::: "memory")
#define CP_WAIT(n)   asm volatile("cp.async.wait_group %0;" :: "n"(n) : "memory")

__device__ __forceinline__ void mma_tf32(float* c, const uint32_t* a, const uint32_t* b) {
    asm volatile(
        "mma.sync.aligned.m16n8k8.row.col.f32.tf32.tf32.f32 "
        "{%0,%1,%2,%3}, {%4,%5,%6,%7}, {%8,%9}, {%0,%1,%2,%3};"
        : "+f"(c[0]), "+f"(c[1]), "+f"(c[2]), "+f"(c[3])
        : "r"(a[0]), "r"(a[1]), "r"(a[2]), "r"(a[3]), "r"(b[0]), "r"(b[1]));
}

// ============================================================================
// K1: h = x @ W + b   (8192x128 @ 128x128)
// ============================================================================
__global__ void __launch_bounds__(128) xw_kernel(const float* __restrict__ x,
                                                 const float* __restrict__ W,
                                                 const float* __restrict__ bias) {
    __shared__ float xs[32][128];
    const int r0 = blockIdx.x * 32;
    const int tid = threadIdx.x;

    const float4* xsrc = (const float4*)(x + (size_t)r0 * DD);
    float4* xdst = (float4*)&xs[0][0];
    for (int idx = tid; idx < 32 * 32; idx += 128) xdst[idx] = xsrc[idx];
    __syncthreads();

    const int n = tid;
    const float b = bias[n];
    float acc[32];
#pragma unroll
    for (int r = 0; r < 32; r++) acc[r] = b;

    for (int k = 0; k < 128; k++) {
        float w = W[k * DD + n];
#pragma unroll
        for (int r = 0; r < 32; r++) acc[r] = fmaf(xs[r][k], w, acc[r]);
    }
#pragma unroll
    for (int r = 0; r < 32; r++) g_h[(size_t)(r0 + r) * DD + n] = acc[r];
}

// ============================================================================
// K2: rowsum(A) with self-loop -> d, e   (one block per row)
// ============================================================================
__global__ void __launch_bounds__(256) rowsum_kernel(const float* __restrict__ A) {
    const int i = blockIdx.x;
    const int tid = threadIdx.x;
    const float4* row = (const float4*)(A + (size_t)i * NN);
    float s = 0.f;
#pragma unroll 4
    for (int c = tid; c < NN / 4; c += 256) {
        float4 v = row[c];
        s += (v.x + v.y) + (v.z + v.w);
    }
#pragma unroll
    for (int o = 16; o; o >>= 1) s += __shfl_down_sync(0xffffffffu, s, o);
    __shared__ float red[8];
    if ((tid & 31) == 0) red[tid >> 5] = s;
    __syncthreads();
    if (tid == 0) {
        float tot = 0.f;
#pragma unroll
        for (int w = 0; w < 8; w++) tot += red[w];
        float aii = A[(size_t)i * NN + i];
        tot = tot - aii + 1.0f;           // exact: small-integer arithmetic in f32
        float di = rsqrtf(tot);
        g_d[i] = di;
        g_e[i] = di * (1.0f - aii);
    }
}

// ============================================================================
// K3: g = D*h (fp32) and gT = tf32_rna(g)^T  (GEMM B operand, 128 x 8192)
// ============================================================================
__global__ void __launch_bounds__(256) scale_transpose_kernel() {
    __shared__ float t[32][33];
    const int i0 = blockIdx.x * 32;
    const int n0 = blockIdx.y * 32;
    const int tx = threadIdx.x, ty = threadIdx.y;

    for (int r = ty; r < 32; r += 8) {
        int i = i0 + r;
        float v = g_h[(size_t)i * DD + n0 + tx] * g_d[i];
        g_g[(size_t)i * DD + n0 + tx] = v;
        t[r][tx] = v;
    }
    __syncthreads();
    for (int r = ty; r < 32; r += 8) {
        float v = t[tx][r];                       // element (row i0+tx, col n0+r)
        uint32_t tf;
        asm("cvt.rna.tf32.f32 %0, %1;" : "=r"(tf) : "f"(v));
        g_gT[(size_t)(n0 + r) * NN + i0 + tx] = __uint_as_float(tf);
    }
}

// ============================================================================
// K4: out = D * (A @ g) + diag(e) * g
//   tf32 mma.sync GEMM: CTA tile 64x128, 8 warps (2m x 4n), warp tile 32x32,
//   BK=32, 4-stage cp.async pipeline.
// ============================================================================
__global__ void __launch_bounds__(GTHREADS, 1) gcn_gemm(
    const float* __restrict__ A, float* __restrict__ out)
{
    extern __shared__ float smem[];
    const int tid = threadIdx.x;
    const int wid = tid >> 5;
    const int lane = tid & 31;
    const int gid = lane >> 2;     // group id 0..7
    const int tg  = lane & 3;      // thread-in-group 0..3
    const int m0 = blockIdx.x * BM;

    const int wm = wid & 1;        // 2 warps along M
    const int wn = wid >> 1;       // 4 warps along N
    const int mwb = wm * 32;       // warp m-offset in tile
    const int nwb = wn * 32;       // warp n-offset in tile

    const uint32_t smem_base = smem_u32(smem);

    // ---------------- cp.async stage fill ----------------
    // 1536 chunks of 16B per stage: A = 512 (64 rows x 8), B = 1024 (128 x 8)
    auto issue_stage = [&](int kt, int slot) {
        const int k0 = kt * BK;
        const uint32_t sA = smem_base + (uint32_t)(slot * STAGE_FLOATS) * 4u;
        const uint32_t sB = sA + AS_FLOATS * 4u;
#pragma unroll
        for (int j = 0; j < 6; j++) {
            int c = tid + j * GTHREADS;
            if (c < 512) {
                int r = c >> 3, c8 = c & 7;
                cp16(sA + (uint32_t)(r * APAD + c8 * 4) * 4u,
                     A + (size_t)(m0 + r) * NN + k0 + c8 * 4);
            } else {
                int cb = c - 512;
                int r = cb >> 3, c8 = cb & 7;
                cp16(sB + (uint32_t)(r * APAD + c8 * 4) * 4u,
                     g_gT + (size_t)r * NN + k0 + c8 * 4);
            }
        }
    };

    float c[2][4][4];
#pragma unroll
    for (int mf = 0; mf < 2; mf++)
#pragma unroll
        for (int nf = 0; nf < 4; nf++)
#pragma unroll
            for (int q = 0; q < 4; q++) c[mf][nf][q] = 0.f;

    // prefetch first STAGES-1 stages
#pragma unroll
    for (int s = 0; s < STAGES - 1; s++) {
        issue_stage(s, s);
        CP_COMMIT();
    }

    for (int kt = 0; kt < NKT; kt++) {
        CP_WAIT(STAGES - 2);
        __syncthreads();

        // prefetch stage kt+STAGES-1 into slot (kt+STAGES-1)%STAGES
        int nxt = kt + STAGES - 1;
        if (nxt < NKT) issue_stage(nxt, nxt & (STAGES - 1));
        CP_COMMIT();

        const int slot = kt & (STAGES - 1);
        const uint32_t* sA = (const uint32_t*)(smem + slot * STAGE_FLOATS);
        const uint32_t* sB = sA + AS_FLOATS;

#pragma unroll
        for (int kk = 0; kk < 4; kk++) {
            const int k = kk * 8;
            uint32_t a[2][4], b[4][2];
#pragma unroll
            for (int mf = 0; mf < 2; mf++) {
                int row = mwb + mf * 16 + gid;
                a[mf][0] = sA[row * APAD + k + tg];
                a[mf][1] = sA[(row + 8) * APAD + k + tg];
                a[mf][2] = sA[row * APAD + k + tg + 4];
                a[mf][3] = sA[(row + 8) * APAD + k + tg + 4];
            }
#pragma unroll
            for (int nf = 0; nf < 4; nf++) {
                int brow = nwb + nf * 8 + gid;
                b[nf][0] = sB[brow * APAD + k + tg];
                b[nf][1] = sB[brow * APAD + k + tg + 4];
            }
#pragma unroll
            for (int mf = 0; mf < 2; mf++)
#pragma unroll
                for (int nf = 0; nf < 4; nf++)
                    mma_tf32(c[mf][nf], a[mf], b[nf]);
        }
        __syncthreads();
    }

    // ---------------- epilogue ----------------
#pragma unroll
    for (int mf = 0; mf < 2; mf++) {
        int i0r = m0 + mwb + mf * 16 + gid;
        int i1r = i0r + 8;
        float d0 = g_d[i0r], e0 = g_e[i0r];
        float d1 = g_d[i1r], e1 = g_e[i1r];
#pragma unroll
        for (int nf = 0; nf < 4; nf++) {
            int n = nwb + nf * 8 + tg * 2;
            const float2 gv0 = *(const float2*)(g_g + (size_t)i0r * DD + n);
            const float2 gv1 = *(const float2*)(g_g + (size_t)i1r * DD + n);
            float2 o0, o1;
            o0.x = d0 * c[mf][nf][0] + e0 * gv0.x;
            o0.y = d0 * c[mf][nf][1] + e0 * gv0.y;
            o1.x = d1 * c[mf][nf][2] + e1 * gv1.x;
            o1.y = d1 * c[mf][nf][3] + e1 * gv1.y;
            *(float2*)(out + (size_t)i0r * DD + n) = o0;
            *(float2*)(out + (size_t)i1r * DD + n) = o1;
        }
    }
}

// ============================================================================
// Host side
// ============================================================================
extern "C" void kernel_launch(void* const* d_in, const int* in_sizes, int n_in,
                              void* d_out, int out_size) {
    const float* A    = (const float*)d_in[0];
    const float* x    = (const float*)d_in[1];
    const float* W    = (const float*)d_in[2];
    const float* bias = (const float*)d_in[3];
    float* out = (float*)d_out;

    cudaFuncSetAttribute(gcn_gemm, cudaFuncAttributeMaxDynamicSharedMemorySize, SMEM_TOTAL);

    xw_kernel<<<NN / 32, 128>>>(x, W, bias);
    rowsum_kernel<<<NN, 256>>>(A);
    scale_transpose_kernel<<<dim3(NN / 32, DD / 32), dim3(32, 8)>>>();
    gcn_gemm<<<NN / BM, GTHREADS, SMEM_TOTAL>>>(A, out);
}

// round 4
// speedup vs baseline: 1.0154x; 1.0154x over previous
#include <cuda_runtime.h>
#include <cuda.h>
#include <cstdint>

// ============================================================================
// Problem constants
// ============================================================================
#define NN      8192
#define DD      128

// GEMM config (Ampere-style mma.sync tf32; baseline PTX, compiles for sm_100)
#define BM      64
#define BN      128
#define BK      32
#define STAGES  5
#define NKT     (NN / BK)      // 256 K iterations
#define GTHREADS 256

// SMEM tile strides (floats); +4 pad keeps LDS conflict-free and 16B-aligned rows
#define APAD    36             // 32 + 4
#define AS_FLOATS (BM * APAD)          // 2304
#define BS_FLOATS (BN * APAD)          // 4608
#define STAGE_FLOATS (AS_FLOATS + BS_FLOATS)   // 6912
#define SMEM_TOTAL (STAGES * STAGE_FLOATS * 4) // 138240 bytes

// ============================================================================
// Scratch (device globals; allocation-free)
// ============================================================================
__device__ __align__(1024) float g_h[NN * DD];
__device__ __align__(1024) float g_g[NN * DD];
__device__ __align__(1024) float g_gT[DD * NN];
__device__ __align__(128)  float g_d[NN];
__device__ __align__(128)  float g_e[NN];

// ============================================================================
// PTX helpers
// ============================================================================
__device__ __forceinline__ uint32_t smem_u32(const void* p) {
    uint32_t a;
    asm("{ .reg .u64 t; cvta.to.shared.u64 t, %1; cvt.u32.u64 %0, t; }" : "=r"(a) : "l"(p));
    return a;
}

__device__ __forceinline__ void cp16(uint32_t dst, const void* src) {
    asm volatile("cp.async.cg.shared.global [%0], [%1], 16;" :: "r"(dst), "l"(src));
}

#define CP_COMMIT()  asm volatile("cp.async.commit_group;" ::: "memory")
#define CP_WAIT(n)   asm volatile("cp.async.wait_group %0;" :: "n"(n) : "memory")

__device__ __forceinline__ void mma_tf32(float* c, const uint32_t* a, const uint32_t* b) {
    asm volatile(
        "mma.sync.aligned.m16n8k8.row.col.f32.tf32.tf32.f32 "
        "{%0,%1,%2,%3}, {%4,%5,%6,%7}, {%8,%9}, {%0,%1,%2,%3};"
        : "+f"(c[0]), "+f"(c[1]), "+f"(c[2]), "+f"(c[3])
        : "r"(a[0]), "r"(a[1]), "r"(a[2]), "r"(a[3]), "r"(b[0]), "r"(b[1]));
}

// ============================================================================
// K1: h = x @ W + b   (8192x128 @ 128x128)
// ============================================================================
__global__ void __launch_bounds__(128) xw_kernel(const float* __restrict__ x,
                                                 const float* __restrict__ W,
                                                 const float* __restrict__ bias) {
    __shared__ float xs[32][128];
    const int r0 = blockIdx.x * 32;
    const int tid = threadIdx.x;

    const float4* xsrc = (const float4*)(x + (size_t)r0 * DD);
    float4* xdst = (float4*)&xs[0][0];
    for (int idx = tid; idx < 32 * 32; idx += 128) xdst[idx] = xsrc[idx];
    __syncthreads();

    const int n = tid;
    const float b = bias[n];
    float acc[32];
#pragma unroll
    for (int r = 0; r < 32; r++) acc[r] = b;

    for (int k = 0; k < 128; k++) {
        float w = W[k * DD + n];
#pragma unroll
        for (int r = 0; r < 32; r++) acc[r] = fmaf(xs[r][k], w, acc[r]);
    }
#pragma unroll
    for (int r = 0; r < 32; r++) g_h[(size_t)(r0 + r) * DD + n] = acc[r];
}

// ============================================================================
// K2: rowsum(A) with self-loop -> d, e   (one block per row)
// ============================================================================
__global__ void __launch_bounds__(256) rowsum_kernel(const float* __restrict__ A) {
    const int i = blockIdx.x;
    const int tid = threadIdx.x;
    const float4* row = (const float4*)(A + (size_t)i * NN);
    float s = 0.f;
#pragma unroll 4
    for (int c = tid; c < NN / 4; c += 256) {
        float4 v = row[c];
        s += (v.x + v.y) + (v.z + v.w);
    }
#pragma unroll
    for (int o = 16; o; o >>= 1) s += __shfl_down_sync(0xffffffffu, s, o);
    __shared__ float red[8];
    if ((tid & 31) == 0) red[tid >> 5] = s;
    __syncthreads();
    if (tid == 0) {
        float tot = 0.f;
#pragma unroll
        for (int w = 0; w < 8; w++) tot += red[w];
        float aii = A[(size_t)i * NN + i];
        tot = tot - aii + 1.0f;           // exact: small-integer arithmetic in f32
        float di = rsqrtf(tot);
        g_d[i] = di;
        g_e[i] = di * (1.0f - aii);
    }
}

// ============================================================================
// K3: g = D*h (fp32) and gT = tf32_rna(g)^T  (GEMM B operand, 128 x 8192)
// ============================================================================
__global__ void __launch_bounds__(256) scale_transpose_kernel() {
    __shared__ float t[32][33];
    const int i0 = blockIdx.x * 32;
    const int n0 = blockIdx.y * 32;
    const int tx = threadIdx.x, ty = threadIdx.y;

    for (int r = ty; r < 32; r += 8) {
        int i = i0 + r;
        float v = g_h[(size_t)i * DD + n0 + tx] * g_d[i];
        g_g[(size_t)i * DD + n0 + tx] = v;
        t[r][tx] = v;
    }
    __syncthreads();
    for (int r = ty; r < 32; r += 8) {
        float v = t[tx][r];                       // element (row i0+tx, col n0+r)
        uint32_t tf;
        asm("cvt.rna.tf32.f32 %0, %1;" : "=r"(tf) : "f"(v));
        g_gT[(size_t)(n0 + r) * NN + i0 + tx] = __uint_as_float(tf);
    }
}

// ============================================================================
// K4: out = D * (A @ g) + diag(e) * g
//   tf32 mma.sync GEMM: CTA tile 64x128, 8 warps (2m x 4n), warp tile 32x32,
//   BK=32, 5-stage cp.async pipeline, register-double-buffered fragments,
//   single __syncthreads per K iteration.
// ============================================================================
__global__ void __launch_bounds__(GTHREADS, 1) gcn_gemm(
    const float* __restrict__ A, float* __restrict__ out)
{
    extern __shared__ float smem[];
    const int tid = threadIdx.x;
    const int wid = tid >> 5;
    const int lane = tid & 31;
    const int gid = lane >> 2;     // group id 0..7
    const int tg  = lane & 3;      // thread-in-group 0..3
    const int m0 = blockIdx.x * BM;

    const int wm = wid & 1;        // 2 warps along M
    const int wn = wid >> 1;       // 4 warps along N
    const int mwb = wm * 32;       // warp m-offset in tile
    const int nwb = wn * 32;       // warp n-offset in tile

    const uint32_t smem_base = smem_u32(smem);

    // ---------------- cp.async stage fill ----------------
    // 1536 chunks of 16B per stage: A = 512 (64 rows x 8), B = 1024 (128 x 8)
    auto issue_stage = [&](int kt, int slot) {
        const int k0 = kt * BK;
        const uint32_t sA = smem_base + (uint32_t)(slot * STAGE_FLOATS) * 4u;
        const uint32_t sB = sA + AS_FLOATS * 4u;
#pragma unroll
        for (int j = 0; j < 6; j++) {
            int c = tid + j * GTHREADS;
            if (c < 512) {
                int r = c >> 3, c8 = c & 7;
                cp16(sA + (uint32_t)(r * APAD + c8 * 4) * 4u,
                     A + (size_t)(m0 + r) * NN + k0 + c8 * 4);
            } else {
                int cb = c - 512;
                int r = cb >> 3, c8 = cb & 7;
                cp16(sB + (uint32_t)(r * APAD + c8 * 4) * 4u,
                     g_gT + (size_t)r * NN + k0 + c8 * 4);
            }
        }
    };

    float c[2][4][4];
#pragma unroll
    for (int mf = 0; mf < 2; mf++)
#pragma unroll
        for (int nf = 0; nf < 4; nf++)
#pragma unroll
            for (int q = 0; q < 4; q++) c[mf][nf][q] = 0.f;

    // prefetch first STAGES-1 stages
#pragma unroll
    for (int s = 0; s < STAGES - 1; s++) {
        issue_stage(s, s);
        CP_COMMIT();
    }

    // per-thread base offsets within a stage (in floats)
    const int a_r0 = (mwb + gid) * APAD + tg;            // row mwb+gid
    const int a_r1 = (mwb + 8 + gid) * APAD + tg;        // row mwb+gid+8
    const int a_r2 = (mwb + 16 + gid) * APAD + tg;       // mf=1
    const int a_r3 = (mwb + 24 + gid) * APAD + tg;
    const int b_r0 = (nwb + gid) * APAD + tg;
    const int b_r1 = (nwb + 8 + gid) * APAD + tg;
    const int b_r2 = (nwb + 16 + gid) * APAD + tg;
    const int b_r3 = (nwb + 24 + gid) * APAD + tg;

    int slot_r = 0;                 // read slot  = kt % STAGES
    int slot_w = STAGES - 1;        // write slot = (kt + STAGES-1) % STAGES

    for (int kt = 0; kt < NKT; kt++) {
        CP_WAIT(STAGES - 2);
        __syncthreads();

        int nxt = kt + STAGES - 1;
        if (nxt < NKT) issue_stage(nxt, slot_w);
        CP_COMMIT();
        if (++slot_w == STAGES) slot_w = 0;

        const uint32_t* sA = (const uint32_t*)(smem + slot_r * STAGE_FLOATS);
        const uint32_t* sB = sA + AS_FLOATS;
        if (++slot_r == STAGES) slot_r = 0;

        uint32_t a[2][2][4], b[2][4][2];    // [buf][...]

        // load kk=0 fragments
        {
            a[0][0][0] = sA[a_r0];     a[0][0][1] = sA[a_r1];
            a[0][0][2] = sA[a_r0 + 4]; a[0][0][3] = sA[a_r1 + 4];
            a[0][1][0] = sA[a_r2];     a[0][1][1] = sA[a_r3];
            a[0][1][2] = sA[a_r2 + 4]; a[0][1][3] = sA[a_r3 + 4];
            b[0][0][0] = sB[b_r0];     b[0][0][1] = sB[b_r0 + 4];
            b[0][1][0] = sB[b_r1];     b[0][1][1] = sB[b_r1 + 4];
            b[0][2][0] = sB[b_r2];     b[0][2][1] = sB[b_r2 + 4];
            b[0][3][0] = sB[b_r3];     b[0][3][1] = sB[b_r3 + 4];
        }

#pragma unroll
        for (int kk = 0; kk < 4; kk++) {
            const int cur = kk & 1;
            const int alt = cur ^ 1;
            if (kk < 3) {
                const int k = (kk + 1) * 8;
                a[alt][0][0] = sA[a_r0 + k];     a[alt][0][1] = sA[a_r1 + k];
                a[alt][0][2] = sA[a_r0 + k + 4]; a[alt][0][3] = sA[a_r1 + k + 4];
                a[alt][1][0] = sA[a_r2 + k];     a[alt][1][1] = sA[a_r3 + k];
                a[alt][1][2] = sA[a_r2 + k + 4]; a[alt][1][3] = sA[a_r3 + k + 4];
                b[alt][0][0] = sB[b_r0 + k];     b[alt][0][1] = sB[b_r0 + k + 4];
                b[alt][1][0] = sB[b_r1 + k];     b[alt][1][1] = sB[b_r1 + k + 4];
                b[alt][2][0] = sB[b_r2 + k];     b[alt][2][1] = sB[b_r2 + k + 4];
                b[alt][3][0] = sB[b_r3 + k];     b[alt][3][1] = sB[b_r3 + k + 4];
            }
#pragma unroll
            for (int mf = 0; mf < 2; mf++)
#pragma unroll
                for (int nf = 0; nf < 4; nf++)
                    mma_tf32(c[mf][nf], a[cur][mf], b[cur][nf]);
        }
    }

    // ---------------- epilogue ----------------
#pragma unroll
    for (int mf = 0; mf < 2; mf++) {
        int i0r = m0 + mwb + mf * 16 + gid;
        int i1r = i0r + 8;
        float d0 = g_d[i0r], e0 = g_e[i0r];
        float d1 = g_d[i1r], e1 = g_e[i1r];
#pragma unroll
        for (int nf = 0; nf < 4; nf++) {
            int n = nwb + nf * 8 + tg * 2;
            const float2 gv0 = *(const float2*)(g_g + (size_t)i0r * DD + n);
            const float2 gv1 = *(const float2*)(g_g + (size_t)i1r * DD + n);
            float2 o0, o1;
            o0.x = d0 * c[mf][nf][0] + e0 * gv0.x;
            o0.y = d0 * c[mf][nf][1] + e0 * gv0.y;
            o1.x = d1 * c[mf][nf][2] + e1 * gv1.x;
            o1.y = d1 * c[mf][nf][3] + e1 * gv1.y;
            *(float2*)(out + (size_t)i0r * DD + n) = o0;
            *(float2*)(out + (size_t)i1r * DD + n) = o1;
        }
    }
}

// ============================================================================
// Host side
// ============================================================================
extern "C" void kernel_launch(void* const* d_in, const int* in_sizes, int n_in,
                              void* d_out, int out_size) {
    const float* A    = (const float*)d_in[0];
    const float* x    = (const float*)d_in[1];
    const float* W    = (const float*)d_in[2];
    const float* bias = (const float*)d_in[3];
    float* out = (float*)d_out;

    cudaFuncSetAttribute(gcn_gemm, cudaFuncAttributeMaxDynamicSharedMemorySize, SMEM_TOTAL);

    xw_kernel<<<NN / 32, 128>>>(x, W, bias);
    rowsum_kernel<<<NN, 256>>>(A);
    scale_transpose_kernel<<<dim3(NN / 32, DD / 32), dim3(32, 8)>>>();
    gcn_gemm<<<NN / BM, GTHREADS, SMEM_TOTAL>>>(A, out);
}